// round 2
// baseline (speedup 1.0000x reference)
#include <cuda_runtime.h>

// HEALPix padding: data [B*12, C, 64, 64] f32, p=2 -> out [B*12, C, 68, 68].
//
// Strategy: a tiny per-launch "build_table" kernel computes, for each of the
// 12*68*68 output spatial positions, the source (face, offset) pair(s).
// face2 >= 0 means blend 0.5*(src1 + src2) (the _tl/_br corner diagonals).
// The main kernel is then a pure gather, one thread per output element.

#define HH 64          // face H = W
#define P  2           // pad
#define PH 68          // HH + 2*P
#define PW 68
#define NPLANE (PH*PW) // 4624
#define NC  256
#define NFACE 12
#define NTAB (NFACE*NPLANE)   // 55488

__device__ int4 g_table[NTAB];

__device__ __forceinline__ int idx64(int r, int c) { return r * HH + c; }

__global__ void build_table_kernel() {
    int t = blockIdx.x * blockDim.x + threadIdx.x;
    if (t >= NTAB) return;
    int f   = t / NPLANE;
    int rem = t - f * NPLANE;
    int i   = rem / PW;
    int j   = rem - i * PW;

    int ii = i - P;        // center-row coord
    int jj = j - P;        // center-col coord
    int rb = i - P - HH;   // bottom-band row
    int jr = j - P - HH;   // right-band col

    int f1 = 0, o1 = 0, f2 = -1, o2 = 0;

    if (f < 4) {
        // ---- north faces: _pn ----
        int n   = f;
        int Ft  = (n + 1) & 3;           // top    (rot90 +1)
        int Ftl = (n + 2) & 3;           // top-left (rot90 2)
        int Fl  = (n + 3) & 3;           // left   (rot90 -1)
        int Fbl = (n + 3) & 3;           // bottom-left
        int Fb  = n + 4;                 // bottom
        int Fbr = n + 8;                 // bottom-right
        int Fr  = 4 + ((n + 1) & 3);     // right
        int Ftr = (n + 1) & 3;           // top-right
        if (i < P) {
            if (j < P)            { f1 = Ftl; o1 = idx64(P-1-i, P-1-j); }          // rot90(tl,2)[-p:,-p:]
            else if (j < P + HH)  { f1 = Ft;  o1 = idx64(jj, P-1-i); }             // rot90(t,1)[-p:,:]
            else                  { f1 = Ftr; o1 = idx64(HH-P+i, jr); }            // tr[-p:,:p]
        } else if (i < P + HH) {
            if (j < P)            { f1 = Fl;  o1 = idx64(P-1-j, ii); }             // rot90(lft,-1)[:,-p:]
            else if (j < P + HH)  { f1 = n;   o1 = idx64(ii, jj); }                // center
            else                  { f1 = Fr;  o1 = idx64(ii, jr); }                // rgt[:, :p]
        } else {
            if (j < P)            { f1 = Fbl; o1 = idx64(rb, HH-P+j); }            // bl[:p,-p:]
            else if (j < P + HH)  { f1 = Fb;  o1 = idx64(rb, jj); }                // b[:p,:]
            else                  { f1 = Fbr; o1 = idx64(rb, jr); }                // br[:p,:p]
        }
    } else if (f < 8) {
        // ---- equator faces: _pe with synthesized _tl / _br corners ----
        int k   = f - 4;
        int Ft  = k;
        int Fl  = (k + 3) & 3;
        int Fbl = 4 + ((k + 3) & 3);
        int Fb  = 8 + ((k + 3) & 3);
        int Fr  = 8 + k;
        int Ftr = 4 + ((k + 1) & 3);
        if (i < P) {
            if (j < P) {
                // _tl(top=Ft, lft=Fl)[i, j]
                if (i == j) {
                    f1 = Ft; o1 = idx64(HH-P+i, 0);
                    f2 = Fl; o2 = idx64(0, HH-P+i);
                } else if (j > i) { f1 = Ft; o1 = idx64(HH-P+i, j-i-1); }
                else              { f1 = Fl; o1 = idx64(i-j-1, HH-P+j); }
            }
            else if (j < P + HH)  { f1 = Ft;  o1 = idx64(HH-P+i, jj); }            // t[-p:,:]
            else                  { f1 = Ftr; o1 = idx64(HH-P+i, jr); }            // tr[-p:,:p]
        } else if (i < P + HH) {
            if (j < P)            { f1 = Fl;  o1 = idx64(ii, HH-P+j); }            // lft[:,-p:]
            else if (j < P + HH)  { f1 = f;   o1 = idx64(ii, jj); }
            else                  { f1 = Fr;  o1 = idx64(ii, jr); }                // rgt[:, :p]
        } else {
            if (j < P)            { f1 = Fbl; o1 = idx64(rb, HH-P+j); }            // bl[:p,-p:]
            else if (j < P + HH)  { f1 = Fb;  o1 = idx64(rb, jj); }                // b[:p,:]
            else {
                // _br(b=Fb, r=Fr)[rb, jr]
                if (rb == jr) {
                    f1 = Fb; o1 = idx64(rb, HH-1);
                    f2 = Fr; o2 = idx64(HH-1, rb);
                } else if (jr < rb) { f1 = Fb; o1 = idx64(rb, HH-rb+jr); }
                else                { f1 = Fr; o1 = idx64(HH-jr+rb, jr); }
            }
        }
    } else {
        // ---- south faces: _ps ----
        int m   = f - 8;
        int Ft  = 4 + ((m + 1) & 3);
        int Ftl = m;
        int Fl  = 4 + m;
        int Fbl = 8 + ((m + 3) & 3);
        int Fb  = 8 + ((m + 3) & 3);     // rot90(b, 1)
        int Fbr = 8 + ((m + 2) & 3);     // rot90(br, 2)
        int Fr  = 8 + ((m + 1) & 3);     // rot90(rgt, -1)
        int Ftr = 8 + ((m + 1) & 3);
        if (i < P) {
            if (j < P)            { f1 = Ftl; o1 = idx64(HH-P+i, HH-P+j); }        // tl[-p:,-p:]
            else if (j < P + HH)  { f1 = Ft;  o1 = idx64(HH-P+i, jj); }            // t[-p:,:]
            else                  { f1 = Ftr; o1 = idx64(HH-P+i, jr); }            // tr[-p:,:p]
        } else if (i < P + HH) {
            if (j < P)            { f1 = Fl;  o1 = idx64(ii, HH-P+j); }            // lft[:,-p:]
            else if (j < P + HH)  { f1 = f;   o1 = idx64(ii, jj); }
            else                  { f1 = Fr;  o1 = idx64(HH-1-jr, ii); }           // rot90(rgt,-1)[:,:p]
        } else {
            if (j < P)            { f1 = Fbl; o1 = idx64(rb, HH-P+j); }            // bl[:p,-p:]
            else if (j < P + HH)  { f1 = Fb;  o1 = idx64(jj, HH-1-rb); }           // rot90(b,1)[:p,:]
            else                  { f1 = Fbr; o1 = idx64(HH-1-rb, HH-1-jr); }      // rot90(br,2)[:p,:p]
        }
    }

    g_table[t] = make_int4(f1, o1, f2, o2);
}

__global__ __launch_bounds__(256)
void pad_kernel(const float* __restrict__ in, float* __restrict__ out, int total) {
    int tid = blockIdx.x * blockDim.x + threadIdx.x;
    if (tid >= total) return;

    // tid = (((b*12 + f)*NC + ch)*PH + i)*PW + j
    int pos  = tid % NPLANE;
    int rest = tid / NPLANE;      // (b*12+f)*NC + ch
    int ch   = rest % NC;
    int bf   = rest / NC;         // b*12 + f
    int f    = bf % NFACE;
    int b    = bf / NFACE;

    int4 e = g_table[f * NPLANE + pos];

    long src1 = ((long)(b * NFACE + e.x) * NC + ch) * (HH * HH) + e.y;
    float v = in[src1];
    if (e.z >= 0) {
        long src2 = ((long)(b * NFACE + e.z) * NC + ch) * (HH * HH) + e.w;
        v = 0.5f * (v + in[src2]);
    }
    out[tid] = v;
}

extern "C" void kernel_launch(void* const* d_in, const int* in_sizes, int n_in,
                              void* d_out, int out_size) {
    const float* in = (const float*)d_in[0];
    float* out = (float*)d_out;

    build_table_kernel<<<(NTAB + 255) / 256, 256>>>();

    int total = out_size;  // 96*256*68*68
    pad_kernel<<<(total + 255) / 256, 256>>>(in, out, total);
}

// round 3
// speedup vs baseline: 2.2662x; 2.2662x over previous
#include <cuda_runtime.h>

// HEALPix padding: data [B*12, 256, 64, 64] f32, p=2 -> out [B*12, 256, 68, 68].
//
// Compact per-position table: uint16 enc = face<<12 | offset (offset in 64x64
// plane). Main kernel: one thread = 4 consecutive output floats (float4 store,
// ushort4 table read, 4 gather loads). The 16 blended diagonal positions per
// batch-plane (equator-face _tl/_br corners) get src1 from the table and are
// then overwritten by a tiny fixup kernel.

#define HH 64
#define P  2
#define PH 68
#define PW 68
#define NPLANE (PH*PW)        // 4624 (divisible by 4)
#define NQPP   (NPLANE/4)     // 1156 quads per plane
#define NC  256
#define NFACE 12
#define NTAB (NFACE*NPLANE)   // 55488

__device__ unsigned short g_tab16[NTAB];

__device__ __forceinline__ int idx64(int r, int c) { return r * HH + c; }

__global__ void build_table_kernel() {
    int t = blockIdx.x * blockDim.x + threadIdx.x;
    if (t >= NTAB) return;
    int f   = t / NPLANE;
    int rem = t - f * NPLANE;
    int i   = rem / PW;
    int j   = rem - i * PW;

    int ii = i - P;
    int jj = j - P;
    int rb = i - P - HH;
    int jr = j - P - HH;

    int f1 = 0, o1 = 0;

    if (f < 4) {
        // north faces: _pn
        int n   = f;
        int Ft  = (n + 1) & 3;
        int Ftl = (n + 2) & 3;
        int Fl  = (n + 3) & 3;
        int Fbl = (n + 3) & 3;
        int Fb  = n + 4;
        int Fbr = n + 8;
        int Fr  = 4 + ((n + 1) & 3);
        int Ftr = (n + 1) & 3;
        if (i < P) {
            if (j < P)            { f1 = Ftl; o1 = idx64(P-1-i, P-1-j); }
            else if (j < P + HH)  { f1 = Ft;  o1 = idx64(jj, P-1-i); }
            else                  { f1 = Ftr; o1 = idx64(HH-P+i, jr); }
        } else if (i < P + HH) {
            if (j < P)            { f1 = Fl;  o1 = idx64(P-1-j, ii); }
            else if (j < P + HH)  { f1 = n;   o1 = idx64(ii, jj); }
            else                  { f1 = Fr;  o1 = idx64(ii, jr); }
        } else {
            if (j < P)            { f1 = Fbl; o1 = idx64(rb, HH-P+j); }
            else if (j < P + HH)  { f1 = Fb;  o1 = idx64(rb, jj); }
            else                  { f1 = Fbr; o1 = idx64(rb, jr); }
        }
    } else if (f < 8) {
        // equator faces: _pe (blend diagonals store src1; fixup overwrites)
        int k   = f - 4;
        int Ft  = k;
        int Fl  = (k + 3) & 3;
        int Fbl = 4 + ((k + 3) & 3);
        int Fb  = 8 + ((k + 3) & 3);
        int Fr  = 8 + k;
        int Ftr = 4 + ((k + 1) & 3);
        if (i < P) {
            if (j < P) {
                if (i == j)       { f1 = Ft; o1 = idx64(HH-P+i, 0); }        // blended later
                else if (j > i)   { f1 = Ft; o1 = idx64(HH-P+i, j-i-1); }
                else              { f1 = Fl; o1 = idx64(i-j-1, HH-P+j); }
            }
            else if (j < P + HH)  { f1 = Ft;  o1 = idx64(HH-P+i, jj); }
            else                  { f1 = Ftr; o1 = idx64(HH-P+i, jr); }
        } else if (i < P + HH) {
            if (j < P)            { f1 = Fl;  o1 = idx64(ii, HH-P+j); }
            else if (j < P + HH)  { f1 = f;   o1 = idx64(ii, jj); }
            else                  { f1 = Fr;  o1 = idx64(ii, jr); }
        } else {
            if (j < P)            { f1 = Fbl; o1 = idx64(rb, HH-P+j); }
            else if (j < P + HH)  { f1 = Fb;  o1 = idx64(rb, jj); }
            else {
                if (rb == jr)     { f1 = Fb; o1 = idx64(rb, HH-1); }         // blended later
                else if (jr < rb) { f1 = Fb; o1 = idx64(rb, HH-rb+jr); }
                else              { f1 = Fr; o1 = idx64(HH-jr+rb, jr); }
            }
        }
    } else {
        // south faces: _ps
        int m   = f - 8;
        int Ft  = 4 + ((m + 1) & 3);
        int Ftl = m;
        int Fl  = 4 + m;
        int Fbl = 8 + ((m + 3) & 3);
        int Fb  = 8 + ((m + 3) & 3);
        int Fbr = 8 + ((m + 2) & 3);
        int Fr  = 8 + ((m + 1) & 3);
        int Ftr = 8 + ((m + 1) & 3);
        if (i < P) {
            if (j < P)            { f1 = Ftl; o1 = idx64(HH-P+i, HH-P+j); }
            else if (j < P + HH)  { f1 = Ft;  o1 = idx64(HH-P+i, jj); }
            else                  { f1 = Ftr; o1 = idx64(HH-P+i, jr); }
        } else if (i < P + HH) {
            if (j < P)            { f1 = Fl;  o1 = idx64(ii, HH-P+j); }
            else if (j < P + HH)  { f1 = f;   o1 = idx64(ii, jj); }
            else                  { f1 = Fr;  o1 = idx64(HH-1-jr, ii); }
        } else {
            if (j < P)            { f1 = Fbl; o1 = idx64(rb, HH-P+j); }
            else if (j < P + HH)  { f1 = Fb;  o1 = idx64(jj, HH-1-rb); }
            else                  { f1 = Fbr; o1 = idx64(HH-1-rb, HH-1-jr); }
        }
    }

    g_tab16[t] = (unsigned short)((f1 << 12) | o1);
}

// Each thread: 4 consecutive output floats. src = (b*12+face)<<20 | ch<<12 | off.
__global__ __launch_bounds__(256)
void pad_kernel(const float* __restrict__ in, float* __restrict__ out, int nquads) {
    int q = blockIdx.x * blockDim.x + threadIdx.x;
    if (q >= nquads) return;

    int posq = q % NQPP;          // quad-in-plane
    int rest = q / NQPP;          // bf*NC + ch
    int ch   = rest & (NC - 1);
    int bf   = rest >> 8;
    int b    = bf / NFACE;
    int fo   = bf - b * NFACE;

    const ushort4 e = *reinterpret_cast<const ushort4*>(&g_tab16[fo * NPLANE + posq * 4]);

    int sbase = ((b * NFACE) << 20) | (ch << 12);

    float4 v;
    v.x = in[sbase + ((e.x >> 12) << 20) + (e.x & 4095)];
    v.y = in[sbase + ((e.y >> 12) << 20) + (e.y & 4095)];
    v.z = in[sbase + ((e.z >> 12) << 20) + (e.z & 4095)];
    v.w = in[sbase + ((e.w >> 12) << 20) + (e.w & 4095)];

    reinterpret_cast<float4*>(out)[q] = v;
}

// Overwrite the 16 blended positions per (b, ch): equator faces k=0..3,
// plane positions (0,0),(1,1),(66,66),(67,67).
__global__ void fixup_kernel(const float* __restrict__ in, float* __restrict__ out, int n) {
    int t = blockIdx.x * blockDim.x + threadIdx.x;
    if (t >= n) return;                    // n = B * NC * 4 * 4
    int slot = t & 3;
    int k    = (t >> 2) & 3;
    int ch   = (t >> 4) & (NC - 1);
    int b    = t >> 12;

    int pos, fA, oA, fB, oB;
    if (slot == 0)      { pos = 0;            fA = k;              oA = idx64(HH-P, 0);   fB = (k+3)&3;        oB = idx64(0, HH-P); }
    else if (slot == 1) { pos = PW + 1;       fA = k;              oA = idx64(HH-1, 0);   fB = (k+3)&3;        oB = idx64(0, HH-1); }
    else if (slot == 2) { pos = 66*PW + 66;   fA = 8+((k+3)&3);    oA = idx64(0, HH-1);   fB = 8+k;            oB = idx64(HH-1, 0); }
    else                { pos = 67*PW + 67;   fA = 8+((k+3)&3);    oA = idx64(1, HH-1);   fB = 8+k;            oB = idx64(HH-1, 1); }

    int sbase = ((b * NFACE) << 20) | (ch << 12);
    float v = 0.5f * (in[sbase + (fA << 20) + oA] + in[sbase + (fB << 20) + oB]);

    long oidx = ((long)(b * NFACE + (4 + k)) * NC + ch) * NPLANE + pos;
    out[oidx] = v;
}

extern "C" void kernel_launch(void* const* d_in, const int* in_sizes, int n_in,
                              void* d_out, int out_size) {
    const float* in = (const float*)d_in[0];
    float* out = (float*)d_out;

    build_table_kernel<<<(NTAB + 255) / 256, 256>>>();

    int nquads = out_size / 4;                 // 96*256*68*68 / 4
    pad_kernel<<<(nquads + 255) / 256, 256>>>(in, out, nquads);

    int nb = (out_size / (NFACE * NC * NPLANE));   // batches B = 8
    int nfix = nb * NC * 4 * 4;
    fixup_kernel<<<(nfix + 255) / 256, 256>>>(in, out, nfix);
}